// round 6
// baseline (speedup 1.0000x reference)
#include <cuda_runtime.h>
#include <math.h>
#include <stdint.h>

#define NB 1024
#define NC 100000
#define THREADS 256

#define TILE_BYTES 10000          // 2500 floats, multiple of 16
#define TILE_F4    625            // float4s per tile
#define NTILES     40             // 40 * 10000 B = 400000 B = one row
#define NBUF       3

// scratch: per-row NLL + completion counter (zero-initialized at load)
static __device__ float g_nll[NB];
static __device__ unsigned int g_done;

__device__ __forceinline__ float ex2_fast(float x) {
    float y;
    asm("ex2.approx.ftz.f32 %0, %1;" : "=f"(y) : "f"(x));
    return y;
}

// 64 * log2(e)
#define K2 92.33248261625200f
#define LOG2E 1.4426950408889634f

__device__ __forceinline__ float term(float v) {
    float c = fminf(fmaxf(v, -1.0f), 1.0f);
    return ex2_fast(fmaf(c, K2, -K2));   // exp(64*c - 64)
}

__device__ __forceinline__ uint32_t smem_u32(const void* p) {
    return (uint32_t)__cvta_generic_to_shared(p);
}

__device__ __forceinline__ void mbar_init(uint32_t mbar, uint32_t count) {
    asm volatile("mbarrier.init.shared.b64 [%0], %1;" :: "r"(mbar), "r"(count) : "memory");
}

__device__ __forceinline__ void mbar_expect_tx(uint32_t mbar, uint32_t bytes) {
    asm volatile("mbarrier.arrive.expect_tx.shared.b64 _, [%0], %1;"
                 :: "r"(mbar), "r"(bytes) : "memory");
}

__device__ __forceinline__ void bulk_g2s(uint32_t dst, const void* src,
                                         uint32_t bytes, uint32_t mbar) {
    asm volatile("cp.async.bulk.shared::cta.global.mbarrier::complete_tx::bytes "
                 "[%0], [%1], %2, [%3];"
                 :: "r"(dst), "l"(src), "r"(bytes), "r"(mbar) : "memory");
}

__device__ __forceinline__ void mbar_wait(uint32_t mbar, uint32_t parity) {
    asm volatile(
        "{\n\t"
        ".reg .pred P;\n\t"
        "WL_%=:\n\t"
        "mbarrier.try_wait.parity.acquire.cta.shared::cta.b64 P, [%0], %1, 0x989680;\n\t"
        "@P bra.uni WD_%=;\n\t"
        "bra.uni WL_%=;\n\t"
        "WD_%=:\n\t"
        "}"
        :: "r"(mbar), "r"(parity) : "memory");
}

__global__ void __launch_bounds__(THREADS)
fused_loss_kernel(const float* __restrict__ x,
                  const int* __restrict__ label,
                  const float* __restrict__ margin,
                  float* __restrict__ out) {
    __shared__ alignas(16) float4 buf[NBUF][TILE_F4];   // 30000 B
    __shared__ uint64_t mbar_store[NBUF];
    __shared__ float red[THREADS / 32];
    __shared__ bool amLast;

    const int row = blockIdx.x;
    const char* gbase = (const char*)(x + (size_t)row * NC);

    uint32_t mbar0 = smem_u32(&mbar_store[0]);

    if (threadIdx.x == 0) {
        #pragma unroll
        for (int b = 0; b < NBUF; b++) mbar_init(mbar0 + 8u * b, 1);
        asm volatile("fence.proxy.async.shared::cta;" ::: "memory");
    }
    __syncthreads();

    // prologue: fill all buffers
    if (threadIdx.x == 0) {
        #pragma unroll
        for (int t = 0; t < NBUF; t++) {
            mbar_expect_tx(mbar0 + 8u * t, TILE_BYTES);
            bulk_g2s(smem_u32(&buf[t][0]), gbase + (size_t)t * TILE_BYTES,
                     TILE_BYTES, mbar0 + 8u * t);
        }
    }

    float s = 0.0f;
    for (int t = 0; t < NTILES; t++) {
        const int b = t % NBUF;
        const int p = (t / NBUF) & 1;
        mbar_wait(mbar0 + 8u * b, (uint32_t)p);

        // consume tile from smem (conflict-free: stride-256 float4)
        #pragma unroll 3
        for (int i = threadIdx.x; i < TILE_F4; i += THREADS) {
            float4 v = buf[b][i];
            s += term(v.x) + term(v.y) + term(v.z) + term(v.w);
        }
        __syncthreads();                 // everyone done reading buf[b]

        if (threadIdx.x == 0 && t + NBUF < NTILES) {
            mbar_expect_tx(mbar0 + 8u * b, TILE_BYTES);
            bulk_g2s(smem_u32(&buf[b][0]),
                     gbase + (size_t)(t + NBUF) * TILE_BYTES,
                     TILE_BYTES, mbar0 + 8u * b);
        }
    }

    // block reduction
    const int lane = threadIdx.x & 31;
    const int wid  = threadIdx.x >> 5;
    #pragma unroll
    for (int o = 16; o; o >>= 1) s += __shfl_xor_sync(0xFFFFFFFFu, s, o);
    if (lane == 0) red[wid] = s;
    __syncthreads();

    if (threadIdx.x == 0) {
        float t = 0.0f;
        #pragma unroll
        for (int w = 0; w < THREADS / 32; w++) t += red[w];
        g_nll[row] = t;                  // store raw exp-sum; fixup in finalize
        __threadfence();
        unsigned int done = atomicAdd(&g_done, 1u);
        amLast = (done == (unsigned int)(NB - 1));
    }
    __syncthreads();

    // last block: per-row target fixup + nll + mean (deterministic order)
    if (amLast) {
        __threadfence();
        float acc = 0.0f;
        #pragma unroll
        for (int k = 0; k < NB / THREADS; k++) {        // 4 rows per thread
            const int r = threadIdx.x + k * THREADS;
            float tsum = g_nll[r];

            int lb = label[r];
            const bool valid = (lb >= 0);
            int tgt = valid ? lb : 0;
            tgt = min(max(tgt, 0), NC - 1);
            const float mg = valid ? margin[r] : 0.0f;

            float xt = x[(size_t)r * NC + tgt];
            float c  = fminf(fmaxf(xt, -1.0f), 1.0f);
            float l_mod = 64.0f * cosf(acosf(c) + mg);

            float stot = tsum - ex2_fast(fmaf(c, K2, -K2))
                              + ex2_fast((l_mod - 64.0f) * LOG2E);

            acc += 64.0f + logf(stot) - l_mod;          // nll
        }

        #pragma unroll
        for (int o = 16; o; o >>= 1) acc += __shfl_xor_sync(0xFFFFFFFFu, acc, o);
        if (lane == 0) red[wid] = acc;
        __syncthreads();
        if (wid == 0) {
            float u = (lane < THREADS / 32) ? red[lane] : 0.0f;
            #pragma unroll
            for (int o = (THREADS / 64); o; o >>= 1)
                u += __shfl_xor_sync(0xFFFFFFFFu, u, o);
            if (lane == 0) {
                out[0] = u * (1.0f / (float)NB);
                g_done = 0;                              // reset for graph replay
            }
        }
    }
}

extern "C" void kernel_launch(void* const* d_in, const int* in_sizes, int n_in,
                              void* d_out, int out_size) {
    const float* x      = (const float*)d_in[0];
    const int*   label  = (const int*)d_in[1];
    const float* margin = (const float*)d_in[2];
    float*       out    = (float*)d_out;

    fused_loss_kernel<<<NB, THREADS>>>(x, label, margin, out);
}

// round 7
// speedup vs baseline: 1.0684x; 1.0684x over previous
#include <cuda_runtime.h>
#include <math.h>

#define NB 1024
#define NC 100000
#define THREADS 256

// scratch: per-row NLL + completion counter (zero-initialized at load)
static __device__ float g_nll[NB];
static __device__ unsigned int g_done;

__device__ __forceinline__ float ex2_fast(float x) {
    float y;
    asm("ex2.approx.ftz.f32 %0, %1;" : "=f"(y) : "f"(x));
    return y;
}

// 64 * log2(e)
#define K2 92.33248261625200f
#define LOG2E 1.4426950408889634f

__device__ __forceinline__ float term(float v) {
    float c = fminf(fmaxf(v, -1.0f), 1.0f);
    return ex2_fast(fmaf(c, K2, -K2));   // exp(64*c - 64)
}

__global__ void __launch_bounds__(THREADS)
fused_loss_kernel(const float* __restrict__ x,
                  const int* __restrict__ label,
                  const float* __restrict__ margin,
                  float* __restrict__ out) {
    const int row = blockIdx.x;
    const float4* __restrict__ p =
        reinterpret_cast<const float4*>(x + (size_t)row * NC);
    const int n4 = NC / 4;  // 25000

    __shared__ float red[THREADS / 32];
    __shared__ float s_xt;          // target-class cosine, captured in-loop
    __shared__ bool amLast;

    // target bookkeeping (uniform across block; label/margin broadcast-load)
    int lb = label[row];
    const bool valid = (lb >= 0);
    int tgt = valid ? lb : 0;
    tgt = min(max(tgt, 0), NC - 1);             // never fabricate OOB address
    const int tgt4 = tgt >> 2;
    const int comp = tgt & 3;

    float s = 0.0f;
    #pragma unroll 4
    for (int i = threadIdx.x; i < n4; i += THREADS) {
        float4 v = p[i];
        if (i == tgt4) {                        // exactly one thread, one iter
            float lo = (comp & 1) ? v.y : v.x;
            float hi = (comp & 1) ? v.w : v.z;
            s_xt = (comp & 2) ? hi : lo;
        }
        s += term(v.x) + term(v.y) + term(v.z) + term(v.w);
    }

    // block reduction
    const int lane = threadIdx.x & 31;
    const int wid  = threadIdx.x >> 5;
    #pragma unroll
    for (int o = 16; o; o >>= 1) s += __shfl_xor_sync(0xFFFFFFFFu, s, o);
    if (lane == 0) red[wid] = s;
    __syncthreads();                            // also orders s_xt

    if (threadIdx.x == 0) {
        float t = 0.0f;
        #pragma unroll
        for (int w = 0; w < THREADS / 32; w++) t += red[w];

        const float mg = valid ? margin[row] : 0.0f;
        float c  = fminf(fmaxf(s_xt, -1.0f), 1.0f);
        float l_mod = 64.0f * cosf(acosf(c) + mg);

        // replace target term: subtract original, add modified
        float stot = t - ex2_fast(fmaf(c, K2, -K2))
                       + ex2_fast((l_mod - 64.0f) * LOG2E);

        g_nll[row] = 64.0f + logf(stot) - l_mod;   // nll

        __threadfence();
        unsigned int done = atomicAdd(&g_done, 1u);
        amLast = (done == (unsigned int)(NB - 1));
    }
    __syncthreads();

    // last block to finish: mean over 1024 contiguous nll values
    if (amLast) {
        __threadfence();
        float acc = 0.0f;
        #pragma unroll
        for (int k = 0; k < NB / THREADS; k++)
            acc += g_nll[threadIdx.x + k * THREADS];

        #pragma unroll
        for (int o = 16; o; o >>= 1) acc += __shfl_xor_sync(0xFFFFFFFFu, acc, o);
        if (lane == 0) red[wid] = acc;
        __syncthreads();
        if (wid == 0) {
            float u = (lane < THREADS / 32) ? red[lane] : 0.0f;
            #pragma unroll
            for (int o = (THREADS / 64); o; o >>= 1)
                u += __shfl_xor_sync(0xFFFFFFFFu, u, o);
            if (lane == 0) {
                out[0] = u * (1.0f / (float)NB);
                g_done = 0;                          // reset for graph replay
            }
        }
    }
}

extern "C" void kernel_launch(void* const* d_in, const int* in_sizes, int n_in,
                              void* d_out, int out_size) {
    const float* x      = (const float*)d_in[0];
    const int*   label  = (const int*)d_in[1];
    const float* margin = (const float*)d_in[2];
    float*       out    = (float*)d_out;

    fused_loss_kernel<<<NB, THREADS>>>(x, label, margin, out);
}

// round 8
// speedup vs baseline: 1.1076x; 1.0366x over previous
#include <cuda_runtime.h>
#include <math.h>

#define NB 1024
#define NC 100000
#define THREADS 256

// scratch: per-row NLL
static __device__ float g_nll[NB];

__device__ __forceinline__ float ex2_fast(float x) {
    float y;
    asm("ex2.approx.ftz.f32 %0, %1;" : "=f"(y) : "f"(x));
    return y;
}

// 64 * log2(e)
#define K2 92.33248261625200f
#define LOG2E 1.4426950408889634f

__device__ __forceinline__ float term(float v) {
    float c = fminf(fmaxf(v, -1.0f), 1.0f);
    return ex2_fast(fmaf(c, K2, -K2));   // exp(64*c - 64)
}

__global__ void __launch_bounds__(THREADS)
row_lse_kernel(const float* __restrict__ x,
               const int* __restrict__ label,
               const float* __restrict__ margin) {
    const int row = blockIdx.x;
    const float4* __restrict__ p =
        reinterpret_cast<const float4*>(x + (size_t)row * NC);
    const int n4 = NC / 4;  // 25000

    float s = 0.0f;
    #pragma unroll 4
    for (int i = threadIdx.x; i < n4; i += THREADS) {
        float4 v = p[i];
        s += term(v.x) + term(v.y) + term(v.z) + term(v.w);
    }

    // block reduction
    __shared__ float red[THREADS / 32];
    const int lane = threadIdx.x & 31;
    const int wid  = threadIdx.x >> 5;
    #pragma unroll
    for (int o = 16; o; o >>= 1) s += __shfl_xor_sync(0xFFFFFFFFu, s, o);
    if (lane == 0) red[wid] = s;
    __syncthreads();

    if (wid == 0) {
        float t = (lane < THREADS / 32) ? red[lane] : 0.0f;
        #pragma unroll
        for (int o = (THREADS / 64); o; o >>= 1)
            t += __shfl_xor_sync(0xFFFFFFFFu, t, o);

        if (lane == 0) {
            int lb = label[row];
            const bool valid = (lb >= 0);
            int tgt = valid ? lb : 0;
            tgt = min(max(tgt, 0), NC - 1);   // never fabricate OOB address
            const float mg = valid ? margin[row] : 0.0f;

            float xt = x[(size_t)row * NC + tgt];
            float c  = fminf(fmaxf(xt, -1.0f), 1.0f);
            float l_mod = 64.0f * cosf(acosf(c) + mg);

            // replace target term: subtract original, add modified
            float stot = t - ex2_fast(fmaf(c, K2, -K2))
                           + ex2_fast((l_mod - 64.0f) * LOG2E);

            // nll = lse - l_mod,  lse = 64 + log(stot)
            g_nll[row] = 64.0f + logf(stot) - l_mod;
        }
    }
}

__global__ void __launch_bounds__(NB)
mean_kernel(float* __restrict__ out) {
    // PDL: we were launched before row_lse_kernel finished; wait for its
    // completion (and memory visibility) before reading g_nll.
#if __CUDA_ARCH__ >= 900
    cudaGridDependencySynchronize();
#endif
    float s = g_nll[threadIdx.x];
    __shared__ float red[NB / 32];
    const int lane = threadIdx.x & 31;
    const int wid  = threadIdx.x >> 5;
    #pragma unroll
    for (int o = 16; o; o >>= 1) s += __shfl_xor_sync(0xFFFFFFFFu, s, o);
    if (lane == 0) red[wid] = s;
    __syncthreads();
    if (wid == 0) {
        float t = (lane < NB / 32) ? red[lane] : 0.0f;
        #pragma unroll
        for (int o = 16; o; o >>= 1) t += __shfl_xor_sync(0xFFFFFFFFu, t, o);
        if (lane == 0) out[0] = t * (1.0f / (float)NB);
    }
}

extern "C" void kernel_launch(void* const* d_in, const int* in_sizes, int n_in,
                              void* d_out, int out_size) {
    const float* x      = (const float*)d_in[0];
    const int*   label  = (const int*)d_in[1];
    const float* margin = (const float*)d_in[2];
    float*       out    = (float*)d_out;

    row_lse_kernel<<<NB, THREADS>>>(x, label, margin);

    // Launch mean_kernel with programmatic stream serialization so its
    // launch overhead overlaps row_lse_kernel's execution.
    cudaLaunchConfig_t cfg = {};
    cfg.gridDim  = dim3(1, 1, 1);
    cfg.blockDim = dim3(NB, 1, 1);
    cfg.dynamicSmemBytes = 0;
    cfg.stream = 0;  // legacy default stream (same as <<<>>> above)
    cudaLaunchAttribute attr[1];
    attr[0].id = cudaLaunchAttributeProgrammaticStreamSerialization;
    attr[0].val.programmaticStreamSerializationAllowed = 1;
    cfg.attrs = attr;
    cfg.numAttrs = 1;

    if (cudaLaunchKernelEx(&cfg, mean_kernel, out) != cudaSuccess) {
        // fallback: plain serialized launch (identical semantics)
        mean_kernel<<<1, NB>>>(out);
    }
}

// round 9
// speedup vs baseline: 1.1280x; 1.0184x over previous
#include <cuda_runtime.h>
#include <math.h>

#define NB 1024
#define NC 100000
#define THREADS 256

// scratch: per-row NLL
static __device__ float g_nll[NB];

__device__ __forceinline__ float ex2_fast(float x) {
    float y;
    asm("ex2.approx.ftz.f32 %0, %1;" : "=f"(y) : "f"(x));
    return y;
}

// 64 * log2(e)
#define K2 92.33248261625200f
#define LOG2E 1.4426950408889634f

__device__ __forceinline__ float term(float v) {
    float c = fminf(fmaxf(v, -1.0f), 1.0f);
    return ex2_fast(fmaf(c, K2, -K2));   // exp(64*c - 64)
}

__global__ void __launch_bounds__(THREADS)
row_lse_kernel(const float* __restrict__ x,
               const int* __restrict__ label,
               const float* __restrict__ margin) {
    const int row = blockIdx.x;
    const float4* __restrict__ p =
        reinterpret_cast<const float4*>(x + (size_t)row * NC);
    const int n4 = NC / 4;  // 25000

    float s = 0.0f;
    // streaming loads (evict-first), deep unroll for high MLP
    #pragma unroll 8
    for (int i = threadIdx.x; i < n4; i += THREADS) {
        float4 v = __ldcs(p + i);
        s += term(v.x) + term(v.y) + term(v.z) + term(v.w);
    }

    // block reduction
    __shared__ float red[THREADS / 32];
    const int lane = threadIdx.x & 31;
    const int wid  = threadIdx.x >> 5;
    #pragma unroll
    for (int o = 16; o; o >>= 1) s += __shfl_xor_sync(0xFFFFFFFFu, s, o);
    if (lane == 0) red[wid] = s;
    __syncthreads();

    if (wid == 0) {
        float t = (lane < THREADS / 32) ? red[lane] : 0.0f;
        #pragma unroll
        for (int o = (THREADS / 64); o; o >>= 1)
            t += __shfl_xor_sync(0xFFFFFFFFu, t, o);

        if (lane == 0) {
            int lb = __ldg(label + row);
            const bool valid = (lb >= 0);
            int tgt = valid ? lb : 0;
            tgt = min(max(tgt, 0), NC - 1);   // never fabricate OOB address
            const float mg = valid ? __ldg(margin + row) : 0.0f;

            float xt = __ldg(x + (size_t)row * NC + tgt);
            float c  = fminf(fmaxf(xt, -1.0f), 1.0f);
            float l_mod = 64.0f * cosf(acosf(c) + mg);

            // replace target term: subtract original, add modified
            float stot = t - ex2_fast(fmaf(c, K2, -K2))
                           + ex2_fast((l_mod - 64.0f) * LOG2E);

            // nll = lse - l_mod,  lse = 64 + log(stot)
            g_nll[row] = 64.0f + logf(stot) - l_mod;
        }
    }
}

__global__ void __launch_bounds__(NB)
mean_kernel(float* __restrict__ out) {
    float s = g_nll[threadIdx.x];
    __shared__ float red[NB / 32];
    const int lane = threadIdx.x & 31;
    const int wid  = threadIdx.x >> 5;
    #pragma unroll
    for (int o = 16; o; o >>= 1) s += __shfl_xor_sync(0xFFFFFFFFu, s, o);
    if (lane == 0) red[wid] = s;
    __syncthreads();
    if (wid == 0) {
        float t = (lane < NB / 32) ? red[lane] : 0.0f;
        #pragma unroll
        for (int o = 16; o; o >>= 1) t += __shfl_xor_sync(0xFFFFFFFFu, t, o);
        if (lane == 0) out[0] = t * (1.0f / (float)NB);
    }
}

extern "C" void kernel_launch(void* const* d_in, const int* in_sizes, int n_in,
                              void* d_out, int out_size) {
    const float* x      = (const float*)d_in[0];
    const int*   label  = (const int*)d_in[1];
    const float* margin = (const float*)d_in[2];
    float*       out    = (float*)d_out;

    row_lse_kernel<<<NB, THREADS>>>(x, label, margin);
    mean_kernel<<<1, NB>>>(out);
}